// round 5
// baseline (speedup 1.0000x reference)
#include <cuda_runtime.h>
#include <cstdint>

// Problem constants
#define B_SZ   1024
#define F_SZ   784
#define OUT_F  1024
#define OR_T   32
#define AND_T  16
#define NLIT   (1 + 2 * F_SZ)   // 1569 literals
#define NBG    (B_SZ / 32)      // 32 batch-groups
#define TBL_WORDS (NLIT * NBG)  // 50208 words = 200832 B
#define TBL_BYTES (TBL_WORDS * 4)

#define OUTS_PER_BLOCK 8
#define NTHREADS 1024
#define W_WORDS (OUTS_PER_BLOCK * OR_T * AND_T)     // 4096 words = 16 KB
#define RES_WORDS (OUTS_PER_BLOCK * 4 * NBG)        // 1024 words (4 quads/out)
#define MBAR_OFF_W (TBL_WORDS + W_WORDS + RES_WORDS + 4)
#define SMEM_BYTES ((MBAR_OFF_W + 4) * 4)           // ~221.4 KB

__device__ __align__(16) uint32_t g_T[TBL_WORDS];

// ---------------------------------------------------------------------------
// Pack kernel: grid (25, 8), 256 threads. Each block: 128 batches x 32
// features. Coalesced loads -> smem transpose -> ballot per (feature, group).
// ---------------------------------------------------------------------------
__global__ __launch_bounds__(256) void pack_kernel(const float* __restrict__ x) {
    __shared__ float tile[128][33];           // +1 pad: conflict-free columns

    const int ft  = blockIdx.x;               // feature tile 0..24
    const int bq  = blockIdx.y;               // batch quad 0..7 (4 bg each)
    const int tid = threadIdx.x;
    const int f0  = ft * 32;
    const int b0  = bq * 128;

    const int c  = tid & 31;
    const int r0 = tid >> 5;                  // 16 rows per thread, stride 8
    const int f  = f0 + c;
    if (f < F_SZ) {
        #pragma unroll
        for (int r = r0; r < 128; r += 8)
            tile[r][c] = x[(size_t)(b0 + r) * F_SZ + f];
    } else {
        #pragma unroll
        for (int r = r0; r < 128; r += 8)
            tile[r][c] = 0.0f;
    }
    __syncthreads();

    // 128 (feature, group) pairs over 8 warps
    const int lane = tid & 31;
    const int w    = tid >> 5;
    #pragma unroll
    for (int p = w; p < 128; p += 8) {
        const int ff = p & 31;                // feature within tile
        const int g  = p >> 5;                // group within quad (0..3)
        const int fg = f0 + ff;
        if (fg >= F_SZ) continue;             // warp-uniform predicate
        uint32_t m = __ballot_sync(0xFFFFFFFFu, tile[g * 32 + lane][ff] != 0.0f);
        if (lane == 0) {
            const int bg = bq * 4 + g;
            g_T[(size_t)(1 + fg) * NBG + bg]        = m;
            g_T[(size_t)(1 + F_SZ + fg) * NBG + bg] = ~m;
        }
    }
    if (ft == 0 && tid < 4) g_T[bq * 4 + tid] = 0xFFFFFFFFu;   // const-true
}

// ---------------------------------------------------------------------------
// Logic kernel: 128 blocks x 1024 threads (32 warps).
//  - TMA bulk-copies the 200KB literal table into smem.
//  - Warp quad (4w..4w+3) co-owns output w; quad-member q handles 8 OR-terms.
//  - Weight reads are uniform LDS.128 (uint4).
// ---------------------------------------------------------------------------
__global__ __launch_bounds__(NTHREADS, 1) void logic_kernel(
    const int* __restrict__ weights, float* __restrict__ out) {

    extern __shared__ uint32_t smem[];
    uint32_t* sT   = smem;
    uint32_t* sw   = smem + TBL_WORDS;
    uint32_t* resb = sw + W_WORDS;
    uint32_t  mbar_addr;
    {
        uint64_t* mb64 = (uint64_t*)(smem + MBAR_OFF_W);
        asm("{ .reg .u64 t; cvta.to.shared.u64 t, %1; cvt.u32.u64 %0, t; }"
            : "=r"(mbar_addr) : "l"((void*)mb64));
    }

    const int tid   = threadIdx.x;
    const int oBase = blockIdx.x * OUTS_PER_BLOCK;

    if (tid == 0) {
        asm volatile("mbarrier.init.shared.b64 [%0], 1;" :: "r"(mbar_addr) : "memory");
    }
    __syncthreads();

    if (tid == 0) {
        asm volatile("mbarrier.arrive.expect_tx.shared.b64 _, [%0], %1;"
                     :: "r"(mbar_addr), "r"((uint32_t)TBL_BYTES) : "memory");
        const char* gsrc = (const char*)g_T;
        uint32_t sdst;
        asm("{ .reg .u64 t; cvta.to.shared.u64 t, %1; cvt.u32.u64 %0, t; }"
            : "=r"(sdst) : "l"((void*)sT));
        const uint32_t chunk = TBL_BYTES / 8;   // 25104 B, multiple of 16
        #pragma unroll
        for (int i = 0; i < 8; ++i) {
            asm volatile(
                "cp.async.bulk.shared::cta.global.mbarrier::complete_tx::bytes "
                "[%0], [%1], %2, [%3];"
                :: "r"(sdst + i * chunk), "l"(gsrc + i * chunk),
                   "r"(chunk), "r"(mbar_addr) : "memory");
        }
    }

    // Stage this block's weights while the DMA runs
    {
        const uint4* wsrc = (const uint4*)(weights + (size_t)oBase * OR_T * AND_T);
        uint4* wdst = (uint4*)sw;
        if (tid < W_WORDS / 4) wdst[tid] = wsrc[tid];   // 1024 uint4 = 1024 thr
    }
    __syncthreads();

    // Wait for table DMA
    {
        uint32_t done;
        asm volatile(
            "{\n\t.reg .pred p;\n\t"
            "mbarrier.try_wait.parity.acquire.cta.shared::cta.b64 p, [%1], 0;\n\t"
            "selp.b32 %0, 1, 0, p;\n\t}"
            : "=r"(done) : "r"(mbar_addr) : "memory");
        if (!done) {
            asm volatile(
                "{\n\t.reg .pred P1;\n\t"
                "WL_%=:\n\t"
                "mbarrier.try_wait.parity.acquire.cta.shared::cta.b64 P1, [%0], 0, 0x989680;\n\t"
                "@P1 bra.uni WD_%=;\n\t"
                "bra.uni WL_%=;\n\t"
                "WD_%=:\n\t}"
                :: "r"(mbar_addr) : "memory");
        }
    }

    // Gather: warp quad -> one output; member q handles terms q*8 .. q*8+7
    const int wid  = tid >> 5;                 // 0..31
    const int lane = tid & 31;                 // batch-group
    const int wi   = wid >> 2;                 // output within block
    const int q    = wid & 3;                  // term quarter

    const uint4* tw4 = (const uint4*)(sw + wi * (OR_T * AND_T) + q * (8 * AND_T));

    uint32_t res = 0;
    #pragma unroll
    for (int t = 0; t < 8; ++t) {
        uint32_t m   = 0xFFFFFFFFu;
        uint32_t orw = 0;
        #pragma unroll
        for (int k4 = 0; k4 < 4; ++k4) {
            const uint4 w4 = tw4[t * 4 + k4];          // uniform LDS.128
            orw |= (w4.x | w4.y | w4.z | w4.w);
            m &= sT[w4.x * NBG + lane];
            m &= sT[w4.y * NBG + lane];
            m &= sT[w4.z * NBG + lane];
            m &= sT[w4.w * NBG + lane];
        }
        if (orw != 0) res |= m;
    }
    resb[(wi * 4 + q) * NBG + lane] = res;
    __syncthreads();

    // Store: thread b handles batch b; 8 contiguous floats (two float4).
    // resb reads are warp-uniform (bg = tid>>5 is constant per warp).
    {
        const int b  = tid;
        const int bg = b >> 5;
        const int j  = b & 31;
        float4 v0, v1;
        #define GETBIT(ow) ((((resb[((ow)*4+0)*NBG + bg] | resb[((ow)*4+1)*NBG + bg] | \
                               resb[((ow)*4+2)*NBG + bg] | resb[((ow)*4+3)*NBG + bg]) >> j) & 1u))
        v0.x = (float)GETBIT(0); v0.y = (float)GETBIT(1);
        v0.z = (float)GETBIT(2); v0.w = (float)GETBIT(3);
        v1.x = (float)GETBIT(4); v1.y = (float)GETBIT(5);
        v1.z = (float)GETBIT(6); v1.w = (float)GETBIT(7);
        #undef GETBIT
        float4* dst = (float4*)(out + (size_t)b * OUT_F + oBase);
        dst[0] = v0;
        dst[1] = v1;
    }
}

// ---------------------------------------------------------------------------
extern "C" void kernel_launch(void* const* d_in, const int* in_sizes, int n_in,
                              void* d_out, int out_size) {
    const float* x       = (const float*)d_in[0];   // (1024, 784) float32
    const int*   weights = (const int*)d_in[1];     // (1024, 32, 16) int32
    float*       out     = (float*)d_out;           // (1024, 1024) float32

    cudaFuncSetAttribute(logic_kernel,
                         cudaFuncAttributeMaxDynamicSharedMemorySize, SMEM_BYTES);

    dim3 pgrid(25, 8);
    pack_kernel<<<pgrid, 256>>>(x);
    logic_kernel<<<OUT_F / OUTS_PER_BLOCK, NTHREADS, SMEM_BYTES>>>(weights, out);
}

// round 6
// speedup vs baseline: 1.0151x; 1.0151x over previous
#include <cuda_runtime.h>
#include <cstdint>

// Problem constants
#define B_SZ   1024
#define F_SZ   784
#define OUT_F  1024
#define OR_T   32
#define AND_T  16
#define NLIT   (1 + 2 * F_SZ)   // 1569 literals
#define NBG    (B_SZ / 32)      // 32 batch-groups
#define TBL_WORDS (NLIT * NBG)  // 50208 words = 200832 B (fits L1D carveout)

__device__ __align__(16) uint32_t g_T[TBL_WORDS];

// ---------------------------------------------------------------------------
// Pack kernel (R3 version — empirically ~1us): grid (25, 32), 128 threads.
// Coalesced 32x32 tile load -> smem transpose -> ballot per feature.
// ---------------------------------------------------------------------------
__global__ __launch_bounds__(128) void pack_kernel(const float* __restrict__ x) {
    __shared__ float tile[32][33];            // +1 pad: conflict-free columns

    const int ft  = blockIdx.x;               // 0..24 (feature tile)
    const int bg  = blockIdx.y;               // 0..31 (batch group)
    const int tid = threadIdx.x;
    const int f0  = ft * 32;

    const int c  = tid & 31;
    const int r0 = tid >> 5;                  // 4 rows per pass
    #pragma unroll
    for (int r = r0; r < 32; r += 4) {
        const int f = f0 + c;
        tile[r][c] = (f < F_SZ) ? x[(size_t)(bg * 32 + r) * F_SZ + f] : 0.0f;
    }
    __syncthreads();

    const int lane = tid & 31;
    const int w    = tid >> 5;
    #pragma unroll
    for (int ff = w; ff < 32; ff += 4) {
        const int f = f0 + ff;
        if (f >= F_SZ) break;                 // warp-uniform
        uint32_t m = __ballot_sync(0xFFFFFFFFu, tile[lane][ff] != 0.0f);
        if (lane == 0) {
            g_T[(size_t)(1 + f) * NBG + bg]        = m;
            g_T[(size_t)(1 + F_SZ + f) * NBG + bg] = ~m;
        }
    }
    if (ft == 0 && tid == 0) g_T[bg] = 0xFFFFFFFFu;   // const-true literal
}

// ---------------------------------------------------------------------------
// Logic kernel: 256 blocks x 512 threads, 2 CTAs/SM (one resident wave).
// NO table staging: gathers go through __ldg; the 200KB table lives in L1D
// (first-touch L2 fills overlap with compute). Warp quad per output, 8
// OR-terms per quad member. Weights staged in 8KB smem, read as LDS.128.
// ---------------------------------------------------------------------------
#define OUTS_PER_BLOCK 4
#define NTHREADS 512
#define W_WORDS (OUTS_PER_BLOCK * OR_T * AND_T)   // 2048 words = 8 KB

__global__ __launch_bounds__(NTHREADS, 2) void logic_kernel(
    const int* __restrict__ weights, float* __restrict__ out) {

    __shared__ uint32_t sw[W_WORDS];                       // 8 KB weights
    __shared__ uint32_t resb[OUTS_PER_BLOCK * 4 * NBG];    // 2 KB results

    const int tid   = threadIdx.x;
    const int oBase = blockIdx.x * OUTS_PER_BLOCK;

    // Stage weights: 512 uint4, one per thread, fully coalesced
    {
        const uint4* wsrc = (const uint4*)(weights + (size_t)oBase * OR_T * AND_T);
        ((uint4*)sw)[tid] = wsrc[tid];
    }
    __syncthreads();

    const int wid  = tid >> 5;                 // 0..15
    const int lane = tid & 31;                 // batch-group
    const int wi   = wid >> 2;                 // output within block (0..3)
    const int q    = wid & 3;                  // term quarter

    const uint4* tw4 = (const uint4*)(sw + wi * (OR_T * AND_T) + q * (8 * AND_T));

    uint32_t res = 0;
    #pragma unroll 2
    for (int t = 0; t < 8; ++t) {
        // Two independent accumulators shorten the AND dependency chains and
        // let the compiler keep many L1 loads in flight.
        uint32_t m0 = 0xFFFFFFFFu, m1 = 0xFFFFFFFFu;
        uint32_t orw = 0;
        #pragma unroll
        for (int k4 = 0; k4 < 4; ++k4) {
            const uint4 w4 = tw4[t * 4 + k4];              // uniform LDS.128
            orw |= (w4.x | w4.y | w4.z | w4.w);
            m0 &= __ldg(&g_T[w4.x * NBG + lane]);
            m1 &= __ldg(&g_T[w4.y * NBG + lane]);
            m0 &= __ldg(&g_T[w4.z * NBG + lane]);
            m1 &= __ldg(&g_T[w4.w * NBG + lane]);
        }
        if (orw != 0) res |= (m0 & m1);
    }
    resb[(wi * 4 + q) * NBG + lane] = res;
    __syncthreads();

    // Store: per batch, 4 contiguous floats (one float4), OR over the 4 quads
    #pragma unroll
    for (int b = tid; b < B_SZ; b += NTHREADS) {           // 2 iterations
        const int bg = b >> 5;
        const int j  = b & 31;
        float4 v;
        #define GETBIT(ow) ((((resb[((ow)*4+0)*NBG + bg] | resb[((ow)*4+1)*NBG + bg] | \
                               resb[((ow)*4+2)*NBG + bg] | resb[((ow)*4+3)*NBG + bg]) >> j) & 1u))
        v.x = (float)GETBIT(0); v.y = (float)GETBIT(1);
        v.z = (float)GETBIT(2); v.w = (float)GETBIT(3);
        #undef GETBIT
        *(float4*)(out + (size_t)b * OUT_F + oBase) = v;
    }
}

// ---------------------------------------------------------------------------
extern "C" void kernel_launch(void* const* d_in, const int* in_sizes, int n_in,
                              void* d_out, int out_size) {
    const float* x       = (const float*)d_in[0];   // (1024, 784) float32
    const int*   weights = (const int*)d_in[1];     // (1024, 32, 16) int32
    float*       out     = (float*)d_out;           // (1024, 1024) float32

    dim3 pgrid(25, 32);
    pack_kernel<<<pgrid, 128>>>(x);
    logic_kernel<<<OUT_F / OUTS_PER_BLOCK, NTHREADS>>>(weights, out);
}